// round 6
// baseline (speedup 1.0000x reference)
#include <cuda_runtime.h>

#define NBODY  63
#define NHINGE 61
#define NSITES 16
#define QDIM   68   // 7 free-joint + 61 hinge
#define BLK    128
#define OPAD   49   // padded output row (floats); gcd(49,32)=1 -> conflict-free STS

// Per-hinge folded constants + site metadata.
struct FKConst {
    float4 Q1[NHINGE];        // body_quat[bid]              (w,x,y,z)
    float4 Q2[NHINGE];        // qmul(body_quat[bid],(0,ax)) (w,x,y,z)
    float4 VC[NHINGE];        // body_pos + jnt_pos - f0
    float4 F1[NHINGE];        // R(Q1)(j - ax(ax.j))
    float4 F2[NHINGE];        // R(Q1)(ax x j)
    float4 SP[NSITES];        // site_pos
    unsigned int mask[NBODY]; // bitmask of sites attached to each body
};
__device__ FKConst g_fk;       // staging, written by fk_init
__constant__ FKConst c_fk;     // read by fk_main via constant port

__global__ void fk_init(const float* __restrict__ body_pos,
                        const float* __restrict__ body_quat,
                        const float* __restrict__ hinge_axis,
                        const float* __restrict__ jnt_pos,
                        const float* __restrict__ site_pos,
                        const int*   __restrict__ site_body) {
    int t = threadIdx.x;
    if (t < NBODY) g_fk.mask[t] = 0u;
    if (t < NHINGE) {
        int bid = t + 2;
        float w1 = body_quat[bid*4+0], x1 = body_quat[bid*4+1];
        float y1 = body_quat[bid*4+2], z1 = body_quat[bid*4+3];
        float ax = hinge_axis[t*3+0], ay = hinge_axis[t*3+1], az = hinge_axis[t*3+2];
        g_fk.Q1[t] = make_float4(w1, x1, y1, z1);
        g_fk.Q2[t] = make_float4(-x1*ax - y1*ay - z1*az,
                                  w1*ax + y1*az - z1*ay,
                                  w1*ay - x1*az + z1*ax,
                                  w1*az + x1*ay - y1*ax);
        float jx = jnt_pos[t*3+0], jy = jnt_pos[t*3+1], jz = jnt_pos[t*3+2];
        // Rodrigues decomposition of R(hinge, theta) * j:
        //   e0 = ax(ax.j), e1 = j - e0, e2 = ax x j
        float d = ax*jx + ay*jy + az*jz;
        float e0x = ax*d, e0y = ay*d, e0z = az*d;
        float e1x = jx - e0x, e1y = jy - e0y, e1z = jz - e0z;
        float e2x = ay*jz - az*jy, e2y = az*jx - ax*jz, e2z = ax*jy - ay*jx;
        // f_i = R(Q1) e_i   (qrot by body_quat)
        auto qrot = [&](float vx, float vy, float vz, float& ox, float& oy, float& oz) {
            float tx = 2.f*(y1*vz - z1*vy);
            float ty = 2.f*(z1*vx - x1*vz);
            float tz = 2.f*(x1*vy - y1*vx);
            ox = vx + w1*tx + (y1*tz - z1*ty);
            oy = vy + w1*ty + (z1*tx - x1*tz);
            oz = vz + w1*tz + (x1*ty - y1*tx);
        };
        float f0x,f0y,f0z, f1x,f1y,f1z, f2x,f2y,f2z;
        qrot(e0x,e0y,e0z, f0x,f0y,f0z);
        qrot(e1x,e1y,e1z, f1x,f1y,f1z);
        qrot(e2x,e2y,e2z, f2x,f2y,f2z);
        g_fk.VC[t] = make_float4(body_pos[bid*3+0] + jx - f0x,
                                 body_pos[bid*3+1] + jy - f0y,
                                 body_pos[bid*3+2] + jz - f0z, 0.f);
        g_fk.F1[t] = make_float4(f1x, f1y, f1z, 0.f);
        g_fk.F2[t] = make_float4(f2x, f2y, f2z, 0.f);
    }
    if (t < NSITES)
        g_fk.SP[t] = make_float4(site_pos[t*3+0], site_pos[t*3+1], site_pos[t*3+2], 0.f);
    __syncthreads();
    if (t < NSITES)
        atomicOr(&g_fk.mask[site_body[t]], 1u << t);
}

__global__ __launch_bounds__(BLK, 7)
void fk_main(const float* __restrict__ qpos, float* __restrict__ out, int B) {
    __shared__ __align__(16) float sOut[BLK * OPAD];  // padded staged outputs

    const int base  = blockIdx.x * BLK;
    const int tid   = threadIdx.x;
    const int b     = base + tid;
    const int nElem = (B - base < BLK) ? (B - base) : BLK;

    if (tid < nElem) {
        const float4* q4 = (const float4*)(qpos + (size_t)b * QDIM);
        float* so = sOut + tid * OPAD;

        float4 f0 = q4[0];                 // wp.xyz, quat.w
        float4 f1 = q4[1];                 // quat.xyz, angle[0]
        float wpx = f0.x, wpy = f0.y, wpz = f0.z;
        float qw = f0.w, qx = f1.x, qy = f1.y, qz = f1.z;
        float rn = rsqrtf(qw*qw + qx*qx + qy*qy + qz*qz);
        qw *= rn; qx *= rn; qy *= rn; qz *= rn;

        // Sites attached to body 1
        unsigned int m1 = c_fk.mask[1];
        while (m1) {
            int s = __ffs(m1) - 1; m1 &= m1 - 1;
            float4 sp = c_fk.SP[s];
            float tx = 2.f*(qy*sp.z - qz*sp.y);
            float ty = 2.f*(qz*sp.x - qx*sp.z);
            float tz = 2.f*(qx*sp.y - qy*sp.x);
            so[s*3+0] = wpx + sp.x + qw*tx + (qy*tz - qz*ty);
            so[s*3+1] = wpy + sp.y + qw*ty + (qz*tx - qx*tz);
            so[s*3+2] = wpz + sp.z + qw*tz + (qx*ty - qy*tx);
        }

        auto process = [&](int h, float ang) {
            float sn, cs;
            __sincosf(0.5f * ang, &sn, &cs);

            // lq = cs*Q1 + sn*Q2
            float4 Q1 = c_fk.Q1[h], Q2 = c_fk.Q2[h];
            float lw = cs*Q1.x + sn*Q2.x;
            float lx = cs*Q1.y + sn*Q2.y;
            float ly = cs*Q1.z + sn*Q2.z;
            float lz = cs*Q1.w + sn*Q2.w;

            // nq = wq * lq
            float nw = qw*lw - qx*lx - qy*ly - qz*lz;
            float nx = qw*lx + qx*lw + qy*lz - qz*ly;
            float ny = qw*ly - qx*lz + qy*lw + qz*lx;
            float nz = qw*lz + qx*ly - qy*lx + qz*lw;

            // full-angle sin/cos from half-angle
            float s2   = sn + sn;
            float sinT = s2 * cs;
            float cosT = fmaf(-sn, s2, 1.f);

            // g = VC - cosT*F1 - sinT*F2
            float4 Vc = c_fk.VC[h], F1 = c_fk.F1[h], F2 = c_fk.F2[h];
            float gx = Vc.x - cosT*F1.x - sinT*F2.x;
            float gy = Vc.y - cosT*F1.y - sinT*F2.y;
            float gz = Vc.z - cosT*F1.z - sinT*F2.z;

            // wp += qrot(wq, g)   (rotate by OLD quat)
            float tx = 2.f*(qy*gz - qz*gy);
            float ty = 2.f*(qz*gx - qx*gz);
            float tz = 2.f*(qx*gy - qy*gx);
            wpx += gx + qw*tx + (qy*tz - qz*ty);
            wpy += gy + qw*ty + (qz*tx - qx*tz);
            wpz += gz + qw*tz + (qx*ty - qy*tx);

            qw = nw; qx = nx; qy = ny; qz = nz;

            unsigned int mm = c_fk.mask[h + 2];
            while (mm) {
                int s = __ffs(mm) - 1; mm &= mm - 1;
                float4 sp = c_fk.SP[s];
                float ux = 2.f*(qy*sp.z - qz*sp.y);
                float uy = 2.f*(qz*sp.x - qx*sp.z);
                float uz = 2.f*(qx*sp.y - qy*sp.x);
                so[s*3+0] = wpx + sp.x + qw*ux + (qy*uz - qz*uy);
                so[s*3+1] = wpy + sp.y + qw*uy + (qz*ux - qx*uz);
                so[s*3+2] = wpz + sp.z + qw*uz + (qx*uy - qy*ux);
            }
        };

        // h = 0 from f1.w, then 15 groups of 4 angles via aligned float4 loads
        float4 av = q4[2];
        process(0, f1.w);
        #pragma unroll 1
        for (int g = 0; g < 15; ++g) {
            float4 cur = av;
            if (g < 14) av = q4[3 + g];
            process(4*g + 1, cur.x);
            process(4*g + 2, cur.y);
            process(4*g + 3, cur.z);
            process(4*g + 4, cur.w);
        }
    }

    __syncthreads();

    // Cooperative coalesced store: gather from padded rows, STG.128 contiguous
    {
        float4* ov = (float4*)(out + (size_t)base * 48);
        int total4 = nElem * 12;   // 12 float4 per element
        for (int i = tid; i < total4; i += BLK) {
            int e = i / 12;
            int j = i - e * 12;
            const float* src = sOut + e * OPAD + j * 4;
            ov[i] = make_float4(src[0], src[1], src[2], src[3]);
        }
    }
}

extern "C" void kernel_launch(void* const* d_in, const int* in_sizes, int n_in,
                              void* d_out, int out_size) {
    const float* qpos       = (const float*)d_in[0];
    const float* body_pos   = (const float*)d_in[1];
    const float* body_quat  = (const float*)d_in[2];
    const float* hinge_axis = (const float*)d_in[3];
    const float* jnt_pos    = (const float*)d_in[4];
    const float* site_pos   = (const float*)d_in[5];
    const int*   site_body  = (const int*)d_in[7];

    int B = in_sizes[0] / QDIM;

    static int carveout_set = 0;
    if (!carveout_set) {
        cudaFuncSetAttribute(fk_main, cudaFuncAttributePreferredSharedMemoryCarveout, 100);
        carveout_set = 1;
    }

    fk_init<<<1, 64>>>(body_pos, body_quat, hinge_axis, jnt_pos, site_pos, site_body);

    // Stage computed constants into the constant bank (D2D memcpy graph node)
    void* g_addr = nullptr;
    cudaGetSymbolAddress(&g_addr, g_fk);
    cudaMemcpyToSymbolAsync(c_fk, g_addr, sizeof(FKConst), 0, cudaMemcpyDeviceToDevice);

    fk_main<<<(B + BLK - 1) / BLK, BLK>>>(qpos, (float*)d_out, B);
}

// round 7
// speedup vs baseline: 1.6572x; 1.6572x over previous
#include <cuda_runtime.h>

#define NBODY  63
#define NHINGE 61
#define NSITES 16
#define QDIM   68   // 7 free-joint + 61 hinge
#define BLK    128
#define OPAD   49   // padded output row (floats); gcd(49,32)=1 -> conflict-free STS

// Per-hinge folded constants + site metadata, produced by fk_init each launch.
struct FKConst {
    float4 Q1[NHINGE];        // body_quat[bid]              (w,x,y,z)
    float4 Q2[NHINGE];        // qmul(body_quat[bid],(0,ax)) (w,x,y,z)
    float4 VC[NHINGE];        // body_pos + jnt_pos - f0
    float4 F1[NHINGE];        // R(Q1)(j - ax(ax.j))
    float4 F2[NHINGE];        // R(Q1)(ax x j)
    float4 SP[NSITES];        // site_pos
    unsigned int mask[NBODY]; // bitmask of sites attached to each body
};
__device__ FKConst g_fk;

__global__ void fk_init(const float* __restrict__ body_pos,
                        const float* __restrict__ body_quat,
                        const float* __restrict__ hinge_axis,
                        const float* __restrict__ jnt_pos,
                        const float* __restrict__ site_pos,
                        const int*   __restrict__ site_body) {
    int t = threadIdx.x;
    if (t < NBODY) g_fk.mask[t] = 0u;
    if (t < NHINGE) {
        int bid = t + 2;
        float w1 = body_quat[bid*4+0], x1 = body_quat[bid*4+1];
        float y1 = body_quat[bid*4+2], z1 = body_quat[bid*4+3];
        float ax = hinge_axis[t*3+0], ay = hinge_axis[t*3+1], az = hinge_axis[t*3+2];
        g_fk.Q1[t] = make_float4(w1, x1, y1, z1);
        g_fk.Q2[t] = make_float4(-x1*ax - y1*ay - z1*az,
                                  w1*ax + y1*az - z1*ay,
                                  w1*ay - x1*az + z1*ax,
                                  w1*az + x1*ay - y1*ax);
        float jx = jnt_pos[t*3+0], jy = jnt_pos[t*3+1], jz = jnt_pos[t*3+2];
        // Rodrigues: R(ax,theta) j = e0 + cosT*e1 + sinT*e2
        float d = ax*jx + ay*jy + az*jz;
        float e0x = ax*d, e0y = ay*d, e0z = az*d;
        float e1x = jx - e0x, e1y = jy - e0y, e1z = jz - e0z;
        float e2x = ay*jz - az*jy, e2y = az*jx - ax*jz, e2z = ax*jy - ay*jx;
        auto qrot = [&](float vx, float vy, float vz, float& ox, float& oy, float& oz) {
            float tx = 2.f*(y1*vz - z1*vy);
            float ty = 2.f*(z1*vx - x1*vz);
            float tz = 2.f*(x1*vy - y1*vx);
            ox = vx + w1*tx + (y1*tz - z1*ty);
            oy = vy + w1*ty + (z1*tx - x1*tz);
            oz = vz + w1*tz + (x1*ty - y1*tx);
        };
        float f0x,f0y,f0z, f1x,f1y,f1z, f2x,f2y,f2z;
        qrot(e0x,e0y,e0z, f0x,f0y,f0z);
        qrot(e1x,e1y,e1z, f1x,f1y,f1z);
        qrot(e2x,e2y,e2z, f2x,f2y,f2z);
        g_fk.VC[t] = make_float4(body_pos[bid*3+0] + jx - f0x,
                                 body_pos[bid*3+1] + jy - f0y,
                                 body_pos[bid*3+2] + jz - f0z, 0.f);
        g_fk.F1[t] = make_float4(f1x, f1y, f1z, 0.f);
        g_fk.F2[t] = make_float4(f2x, f2y, f2z, 0.f);
    }
    if (t < NSITES)
        g_fk.SP[t] = make_float4(site_pos[t*3+0], site_pos[t*3+1], site_pos[t*3+2], 0.f);
    __syncthreads();
    if (t < NSITES)
        atomicOr(&g_fk.mask[site_body[t]], 1u << t);
}

__global__ __launch_bounds__(BLK, 7)
void fk_main(const float* __restrict__ qpos, float* __restrict__ out, int B) {
    __shared__ float4 sQ1[NHINGE], sQ2[NHINGE], sVC[NHINGE], sF1[NHINGE], sF2[NHINGE];
    __shared__ float4 sSP[NSITES];
    __shared__ unsigned int sMask[NBODY];
    __shared__ __align__(16) float sOut[BLK * OPAD];

    for (int i = threadIdx.x; i < NHINGE; i += BLK) {
        sQ1[i] = g_fk.Q1[i]; sQ2[i] = g_fk.Q2[i];
        sVC[i] = g_fk.VC[i]; sF1[i] = g_fk.F1[i]; sF2[i] = g_fk.F2[i];
    }
    if (threadIdx.x < NSITES) sSP[threadIdx.x] = g_fk.SP[threadIdx.x];
    if (threadIdx.x < NBODY)  sMask[threadIdx.x] = g_fk.mask[threadIdx.x];
    __syncthreads();

    const int base  = blockIdx.x * BLK;
    const int tid   = threadIdx.x;
    const int b     = base + tid;
    const int nElem = (B - base < BLK) ? (B - base) : BLK;

    if (tid < nElem) {
        const float4* q4 = (const float4*)(qpos + (size_t)b * QDIM);
        float* so = sOut + tid * OPAD;

        float4 f0 = q4[0];                 // wp.xyz, quat.w
        float4 f1 = q4[1];                 // quat.xyz, angle[0]
        float wpx = f0.x, wpy = f0.y, wpz = f0.z;
        float qw = f0.w, qx = f1.x, qy = f1.y, qz = f1.z;
        float rn = rsqrtf(qw*qw + qx*qx + qy*qy + qz*qz);
        qw *= rn; qx *= rn; qy *= rn; qz *= rn;

        // Sites attached to body 1
        unsigned int m1 = sMask[1];
        while (m1) {
            int s = __ffs(m1) - 1; m1 &= m1 - 1;
            float4 sp = sSP[s];
            float tx = 2.f*(qy*sp.z - qz*sp.y);
            float ty = 2.f*(qz*sp.x - qx*sp.z);
            float tz = 2.f*(qx*sp.y - qy*sp.x);
            so[s*3+0] = wpx + sp.x + qw*tx + (qy*tz - qz*ty);
            so[s*3+1] = wpy + sp.y + qw*ty + (qz*tx - qx*tz);
            so[s*3+2] = wpz + sp.z + qw*tz + (qx*ty - qy*tx);
        }

        // One hinge step; sn/cs are the HALF-angle sincos, precomputed.
        auto process = [&](int h, float sn, float cs) {
            // lq = cs*Q1 + sn*Q2
            float4 Q1 = sQ1[h], Q2 = sQ2[h];
            float lw = cs*Q1.x + sn*Q2.x;
            float lx = cs*Q1.y + sn*Q2.y;
            float ly = cs*Q1.z + sn*Q2.z;
            float lz = cs*Q1.w + sn*Q2.w;

            // nq = wq * lq
            float nw = qw*lw - qx*lx - qy*ly - qz*lz;
            float nx = qw*lx + qx*lw + qy*lz - qz*ly;
            float ny = qw*ly - qx*lz + qy*lw + qz*lx;
            float nz = qw*lz + qx*ly - qy*lx + qz*lw;

            // full-angle sin/cos from half-angle
            float s2   = sn + sn;
            float sinT = s2 * cs;
            float cosT = fmaf(-sn, s2, 1.f);

            // g = VC - cosT*F1 - sinT*F2
            float4 Vc = sVC[h], F1 = sF1[h], F2 = sF2[h];
            float gx = Vc.x - cosT*F1.x - sinT*F2.x;
            float gy = Vc.y - cosT*F1.y - sinT*F2.y;
            float gz = Vc.z - cosT*F1.z - sinT*F2.z;

            // wp += qrot(wq, g)   (rotate by OLD quat)
            float tx = 2.f*(qy*gz - qz*gy);
            float ty = 2.f*(qz*gx - qx*gz);
            float tz = 2.f*(qx*gy - qy*gx);
            wpx += gx + qw*tx + (qy*tz - qz*ty);
            wpy += gy + qw*ty + (qz*tx - qx*tz);
            wpz += gz + qw*tz + (qx*ty - qy*tx);

            qw = nw; qx = nx; qy = ny; qz = nz;

            unsigned int mm = sMask[h + 2];
            while (mm) {
                int s = __ffs(mm) - 1; mm &= mm - 1;
                float4 sp = sSP[s];
                float ux = 2.f*(qy*sp.z - qz*sp.y);
                float uy = 2.f*(qz*sp.x - qx*sp.z);
                float uz = 2.f*(qx*sp.y - qy*sp.x);
                so[s*3+0] = wpx + sp.x + qw*ux + (qy*uz - qz*uy);
                so[s*3+1] = wpy + sp.y + qw*uy + (qz*ux - qx*uz);
                so[s*3+2] = wpz + sp.z + qw*uz + (qx*uy - qy*ux);
            }
        };

        // h = 0 from f1.w, then 15 groups of 4 angles via aligned float4 loads.
        // Per group: batch all 4 MUFU sincos up front so their latency pipelines
        // instead of serializing into the dependent quaternion chain.
        {
            float s0, c0;
            __sincosf(0.5f * f1.w, &s0, &c0);
            process(0, s0, c0);
        }
        float4 av = q4[2];
        #pragma unroll 1
        for (int g = 0; g < 15; ++g) {
            float4 cur = av;
            if (g < 14) av = q4[3 + g];
            float sa, ca, sb, cb, sc, cc, sd, cd;
            __sincosf(0.5f * cur.x, &sa, &ca);
            __sincosf(0.5f * cur.y, &sb, &cb);
            __sincosf(0.5f * cur.z, &sc, &cc);
            __sincosf(0.5f * cur.w, &sd, &cd);
            process(4*g + 1, sa, ca);
            process(4*g + 2, sb, cb);
            process(4*g + 3, sc, cc);
            process(4*g + 4, sd, cd);
        }
    }

    __syncthreads();

    // Cooperative coalesced store: gather from padded rows, STG.128 contiguous
    {
        float4* ov = (float4*)(out + (size_t)base * 48);
        int total4 = nElem * 12;   // 12 float4 per element
        for (int i = tid; i < total4; i += BLK) {
            int e = i / 12;
            int j = i - e * 12;
            const float* src = sOut + e * OPAD + j * 4;
            ov[i] = make_float4(src[0], src[1], src[2], src[3]);
        }
    }
}

extern "C" void kernel_launch(void* const* d_in, const int* in_sizes, int n_in,
                              void* d_out, int out_size) {
    const float* qpos       = (const float*)d_in[0];
    const float* body_pos   = (const float*)d_in[1];
    const float* body_quat  = (const float*)d_in[2];
    const float* hinge_axis = (const float*)d_in[3];
    const float* jnt_pos    = (const float*)d_in[4];
    const float* site_pos   = (const float*)d_in[5];
    const int*   site_body  = (const int*)d_in[7];

    int B = in_sizes[0] / QDIM;

    static int carveout_set = 0;
    if (!carveout_set) {
        cudaFuncSetAttribute(fk_main, cudaFuncAttributePreferredSharedMemoryCarveout, 100);
        carveout_set = 1;
    }

    fk_init<<<1, 64>>>(body_pos, body_quat, hinge_axis, jnt_pos, site_pos, site_body);
    fk_main<<<(B + BLK - 1) / BLK, BLK>>>(qpos, (float*)d_out, B);
}